// round 13
// baseline (speedup 1.0000x reference)
#include <cuda_runtime.h>
#include <cstdint>

#define Hdim 768
#define Nn   50
#define Bb   1024
#define BCH  (Bb / 2)   // 512 per chunk

// ---------------- scratch (static device globals; no allocation) ----------------
__device__ float g_drep[Bb * Hdim];
__device__ float g_wvec[Bb * Hdim];
__device__ float g_R[Bb * Hdim];
__device__ float g_G[Bb * Hdim];
__device__ float g_Qm[Bb];

// ---------------- kernel 1: per-batch reductions over n (float4) + Qm ----------------
__global__ __launch_bounds__(192) void k1_reduce(const float* __restrict__ sv,
                                                 const int* __restrict__ mask,
                                                 const float* __restrict__ qw,
                                                 int b0) {
    const int b = blockIdx.x + b0;
    const int t = threadIdx.x;  // 192 threads, one float4 column each
    __shared__ float sq[Nn];
    if (t < Nn) sq[t] = qw[t] * (mask[b * Nn + t] != 0 ? 1.0f : 0.0f);
    __syncthreads();

    const float4* base = (const float4*)(sv + (size_t)b * Nn * Hdim) + t;
    float adx = 0.f, ady = 0.f, adz = 0.f, adw = 0.f;
    float awx = 0.f, awy = 0.f, awz = 0.f, aww = 0.f;
#pragma unroll 10
    for (int n = 0; n < Nn; n++) {
        float4 v = base[n * (Hdim / 4)];
        float s = sq[n];
        adx += v.x; ady += v.y; adz += v.z; adw += v.w;
        awx = fmaf(s, v.x, awx); awy = fmaf(s, v.y, awy);
        awz = fmaf(s, v.z, awz); aww = fmaf(s, v.w, aww);
    }
    const float inv = 1.0f / (float)Nn;
    float4 od = {adx * inv, ady * inv, adz * inv, adw * inv};
    float4 ow = {awx, awy, awz, aww};
    ((float4*)g_drep)[(size_t)b * (Hdim / 4) + t] = od;
    ((float4*)g_wvec)[(size_t)b * (Hdim / 4) + t] = ow;
    if (t == 0) {
        float Qm = 0.0f;
#pragma unroll
        for (int n = 0; n < Nn; n++) Qm += sq[n];
        g_Qm[b] = Qm;
    }
}

// ---------------- kernel 2: tf32 tensor-core GEMM (NT), cp.async 3-stage, dyn smem ----------------
// z=0: R = d_rep @ W_rel^T   z=1: G = w @ W_sim^T   (per chunk: m_base..m_base+511)
#define BM 64
#define BN 64
#define BK 32
#define KPAD 36
#define NKT (Hdim / BK)  // 24
#define NST 3
#define STAGE_U32 (BM * KPAD)
#define K2_SMEM_BYTES (NST * 2 * STAGE_U32 * 4)  // 55296

__device__ __forceinline__ void cp_async16(void* smem_dst, const void* gmem_src) {
    uint32_t d = (uint32_t)__cvta_generic_to_shared(smem_dst);
    asm volatile("cp.async.cg.shared.global [%0], [%1], 16;" ::"r"(d), "l"(gmem_src));
}
__device__ __forceinline__ void cp_commit() { asm volatile("cp.async.commit_group;"); }
template <int N>
__device__ __forceinline__ void cp_wait() { asm volatile("cp.async.wait_group %0;" ::"n"(N)); }

// round-to-nearest tf32 via bit add (HW truncates low 13 bits of tf32 operand)
__device__ __forceinline__ uint32_t rna_bits(uint32_t x) { return x + 0x1000u; }

__device__ __forceinline__ void mma_tf32(float d[4], const uint32_t a[4], const uint32_t b[2]) {
    asm volatile(
        "mma.sync.aligned.m16n8k8.row.col.f32.tf32.tf32.f32 "
        "{%0,%1,%2,%3}, {%4,%5,%6,%7}, {%8,%9}, {%0,%1,%2,%3};"
        : "+f"(d[0]), "+f"(d[1]), "+f"(d[2]), "+f"(d[3])
        : "r"(a[0]), "r"(a[1]), "r"(a[2]), "r"(a[3]), "r"(b[0]), "r"(b[1]));
}

__global__ __launch_bounds__(256) void k2_gemm(const float* __restrict__ Wrel,
                                               const float* __restrict__ Wsim,
                                               int m_base) {
    extern __shared__ uint32_t smem_dyn[];
    uint32_t* As = smem_dyn;
    uint32_t* Bs = smem_dyn + NST * STAGE_U32;

    const int z = blockIdx.z;
    const float* A  = (z ? g_wvec : g_drep) + (size_t)m_base * Hdim;
    const float* Bm = z ? Wsim   : Wrel;
    float*       C  = (z ? g_G : g_R) + (size_t)m_base * Hdim;

    const int m0 = blockIdx.y * BM;
    const int n0 = blockIdx.x * BN;

    const int tid  = threadIdx.x;
    const int lane = tid & 31;
    const int wid  = tid >> 5;
    const int wm   = wid >> 2;
    const int wn   = wid & 3;
    const int grp  = lane >> 2;
    const int tg   = lane & 3;

    const int lr  = tid >> 3;
    const int lc4 = tid & 7;

    float acc[2][2][4];
#pragma unroll
    for (int mi = 0; mi < 2; mi++)
#pragma unroll
        for (int ni = 0; ni < 2; ni++)
#pragma unroll
            for (int r = 0; r < 4; r++) acc[mi][ni][r] = 0.0f;

#pragma unroll
    for (int pf = 0; pf < 2; pf++) {
        const int k0 = pf * BK;
        uint32_t* Ast = As + pf * STAGE_U32;
        uint32_t* Bst = Bs + pf * STAGE_U32;
#pragma unroll
        for (int p = 0; p < 2; p++) {
            int r = lr + p * 32;
            cp_async16(&Ast[r * KPAD + lc4 * 4], &A[(size_t)(m0 + r) * Hdim + k0 + lc4 * 4]);
            cp_async16(&Bst[r * KPAD + lc4 * 4], &Bm[(size_t)(n0 + r) * Hdim + k0 + lc4 * 4]);
        }
        cp_commit();
    }

    for (int kt = 0; kt < NKT; kt++) {
        const int st = kt % NST;
        if (kt + 2 < NKT) {
            const int k0 = (kt + 2) * BK;
            const int ns = (kt + 2) % NST;
            uint32_t* Ast = As + ns * STAGE_U32;
            uint32_t* Bst = Bs + ns * STAGE_U32;
#pragma unroll
            for (int p = 0; p < 2; p++) {
                int r = lr + p * 32;
                cp_async16(&Ast[r * KPAD + lc4 * 4], &A[(size_t)(m0 + r) * Hdim + k0 + lc4 * 4]);
                cp_async16(&Bst[r * KPAD + lc4 * 4], &Bm[(size_t)(n0 + r) * Hdim + k0 + lc4 * 4]);
            }
            cp_commit();
            cp_wait<2>();
        } else if (kt + 1 < NKT) {
            cp_wait<1>();
        } else {
            cp_wait<0>();
        }
        __syncthreads();

        const uint32_t* Acur = As + st * STAGE_U32;
        const uint32_t* Bcur = Bs + st * STAGE_U32;
#pragma unroll
        for (int kk = 0; kk < 4; kk++) {
            const int c0 = kk * 8 + tg;
            uint32_t afr[2][4];
#pragma unroll
            for (int mi = 0; mi < 2; mi++) {
                int r0 = wm * 32 + mi * 16 + grp;
                afr[mi][0] = rna_bits(Acur[r0 * KPAD + c0]);
                afr[mi][1] = rna_bits(Acur[(r0 + 8) * KPAD + c0]);
                afr[mi][2] = rna_bits(Acur[r0 * KPAD + c0 + 4]);
                afr[mi][3] = rna_bits(Acur[(r0 + 8) * KPAD + c0 + 4]);
            }
            uint32_t bfr[2][2];
#pragma unroll
            for (int ni = 0; ni < 2; ni++) {
                int nr = wn * 16 + ni * 8 + grp;
                bfr[ni][0] = rna_bits(Bcur[nr * KPAD + c0]);
                bfr[ni][1] = rna_bits(Bcur[nr * KPAD + c0 + 4]);
            }
#pragma unroll
            for (int mi = 0; mi < 2; mi++)
#pragma unroll
                for (int ni = 0; ni < 2; ni++) mma_tf32(acc[mi][ni], afr[mi], bfr[ni]);
        }
        __syncthreads();
    }

#pragma unroll
    for (int mi = 0; mi < 2; mi++) {
#pragma unroll
        for (int ni = 0; ni < 2; ni++) {
            int row = m0 + wm * 32 + mi * 16 + grp;
            int col = n0 + wn * 16 + ni * 8 + tg * 2;
            C[(size_t)row * Hdim + col]           = acc[mi][ni][0];
            C[(size_t)row * Hdim + col + 1]       = acc[mi][ni][1];
            C[(size_t)(row + 8) * Hdim + col]     = acc[mi][ni][2];
            C[(size_t)(row + 8) * Hdim + col + 1] = acc[mi][ni][3];
        }
    }
}

// ---------------- kernel 3: fused single-dot per row + epilogue ----------------
// s[b,n] = q_b + mask*( sv[b,n]·V[b] + b00*Qm ),  V[b] = Qm*(R[b]+Wc) + G[b]
__device__ __forceinline__ float wsum(float v) {
    v += __shfl_xor_sync(0xffffffffu, v, 16);
    v += __shfl_xor_sync(0xffffffffu, v, 8);
    v += __shfl_xor_sync(0xffffffffu, v, 4);
    v += __shfl_xor_sync(0xffffffffu, v, 2);
    v += __shfl_xor_sync(0xffffffffu, v, 1);
    return v;
}

__global__ __launch_bounds__(256, 3) void k3_final(const float* __restrict__ sv,
                                                   const int* __restrict__ mask,
                                                   const float* __restrict__ Wc,
                                                   const float* __restrict__ bmat,
                                                   const float* __restrict__ qb,
                                                   float* __restrict__ out,
                                                   int b0) {
    const int b    = b0 + (BCH - 1) - blockIdx.x;   // reverse within chunk
    const int tid  = threadIdx.x;  // 256
    const int lane = tid & 31;
    const int wid  = tid >> 5;

    __shared__ float sDot[64], sM[64];

    if (tid < 64) sM[tid] = (tid < Nn && mask[b * Nn + tid] != 0) ? 1.0f : 0.0f;
    __syncthreads();

    const float Qm = g_Qm[b];

    // fused per-batch vector V = Qm*(R+Wc) + G, register-resident (lane owns lane+32i)
    float4 rv[6];
    {
        const float4* Wc4 = (const float4*)Wc;
        const float4* Rp  = (const float4*)(g_R + (size_t)b * Hdim);
        const float4* Gp  = (const float4*)(g_G + (size_t)b * Hdim);
#pragma unroll
        for (int i = 0; i < 6; i++) {
            int idx = lane + i * 32;
            float4 c = Wc4[idx], r = Rp[idx], g = Gp[idx];
            rv[i].x = fmaf(Qm, r.x + c.x, g.x);
            rv[i].y = fmaf(Qm, r.y + c.y, g.y);
            rv[i].z = fmaf(Qm, r.z + c.z, g.z);
            rv[i].w = fmaf(Qm, r.w + c.w, g.w);
        }
    }

    // pairs (n, n+8): 12 independent LDG.128 in flight, single dot per row
#pragma unroll
    for (int j = 0; j < 3; j++) {
        const int n0 = wid + j * 16;
        const int n1 = n0 + 8;
        const float4* row0 = (const float4*)(sv + ((size_t)b * Nn + n0) * Hdim);
        const float4* row1 = (const float4*)(sv + ((size_t)b * Nn + n1) * Hdim);
        float d0 = 0.f, d1 = 0.f;
#pragma unroll
        for (int i = 0; i < 6; i++) {
            float4 v0 = row0[lane + i * 32];
            float4 v1 = row1[lane + i * 32];
            d0 = fmaf(v0.x, rv[i].x, d0); d0 = fmaf(v0.y, rv[i].y, d0);
            d0 = fmaf(v0.z, rv[i].z, d0); d0 = fmaf(v0.w, rv[i].w, d0);
            d1 = fmaf(v1.x, rv[i].x, d1); d1 = fmaf(v1.y, rv[i].y, d1);
            d1 = fmaf(v1.z, rv[i].z, d1); d1 = fmaf(v1.w, rv[i].w, d1);
        }
        d0 = wsum(d0); d1 = wsum(d1);
        if (lane == 0) { sDot[n0] = d0; sDot[n1] = d1; }
    }
    {   // leftover n = wid + 48 (only wid 0,1)
        const int n = wid + 48;
        if (n < Nn) {
            const float4* row = (const float4*)(sv + ((size_t)b * Nn + n) * Hdim);
            float d = 0.f;
#pragma unroll
            for (int i = 0; i < 6; i++) {
                float4 v = row[lane + i * 32];
                d = fmaf(v.x, rv[i].x, d); d = fmaf(v.y, rv[i].y, d);
                d = fmaf(v.z, rv[i].z, d); d = fmaf(v.w, rv[i].w, d);
            }
            d = wsum(d);
            if (lane == 0) sDot[n] = d;
        }
    }
    __syncthreads();

    if (wid == 0) {
        const float b00 = bmat[0];
        const float qbv = qb[0];
        const bool  v2  = (lane + 32) < Nn;
        const float m1 = sM[lane], m2 = sM[lane + 32];

        const float sn = wsum(m1 + m2);                  // sent_num
        const float bq = b00 * Qm;

        float s1 = qbv + m1 * (sDot[lane] + bq);
        float s2 = v2 ? (qbv + m2 * (sDot[lane + 32] + bq)) : 0.0f;

        const float mu = wsum(s1 + (v2 ? s2 : 0.0f)) * (1.0f / (float)Nn);
        const float d1 = s1 - mu;
        const float d2 = v2 ? (s2 - mu) : 0.0f;
        const float var = wsum(d1 * d1 + d2 * d2) * (1.0f / (float)Nn);
        const float rstd = rsqrtf(var + 1e-6f);

        const float sig1 = 1.0f / (1.0f + expf(-d1 * rstd));
        const float sig2 = 1.0f / (1.0f + expf(-d2 * rstd));

        const float S = wsum(sig1 * m1 + sig2 * m2);
        const float inv = 1.0f / S;
        const float p1 = sig1 * m1 * inv;
        const float p2 = sig2 * m2 * inv;

        float o1 = (1.0f / (1.0f + expf(-(0.2f + 0.8f * p1 * sn)))) * m1;
        out[b * Nn + lane] = o1;
        if (v2) {
            float o2 = (1.0f / (1.0f + expf(-(0.2f + 0.8f * p2 * sn)))) * m2;
            out[b * Nn + lane + 32] = o2;
        }
    }
}

// ---------------- launch: fork-join pipeline (k2 off the critical path) ----------------
extern "C" void kernel_launch(void* const* d_in, const int* in_sizes, int n_in,
                              void* d_out, int out_size) {
    const float* sv   = (const float*)d_in[0];
    const int*   mask = (const int*)d_in[1];
    const float* Wc   = (const float*)d_in[2];
    const float* Wsim = (const float*)d_in[3];
    const float* Wrel = (const float*)d_in[4];
    const float* bmat = (const float*)d_in[5];
    const float* qw   = (const float*)d_in[6];
    const float* qb   = (const float*)d_in[7];
    float*       out  = (float*)d_out;

    cudaFuncSetAttribute(k2_gemm, cudaFuncAttributeMaxDynamicSharedMemorySize, K2_SMEM_BYTES);

    // per-call stream/events (host resources only; kernel_launch runs O(1) times)
    cudaStream_t s1;
    cudaStreamCreateWithFlags(&s1, cudaStreamNonBlocking);
    cudaEvent_t eA, eB, eK0, eK1;
    cudaEventCreateWithFlags(&eA,  cudaEventDisableTiming);
    cudaEventCreateWithFlags(&eB,  cudaEventDisableTiming);
    cudaEventCreateWithFlags(&eK0, cudaEventDisableTiming);
    cudaEventCreateWithFlags(&eK1, cudaEventDisableTiming);

    // main (legacy) stream: k1a -> k1b -> k3(c0) -> k3(c1)
    k1_reduce<<<BCH, 192>>>(sv, mask, qw, 0);        // b 0..511
    cudaEventRecord(eA, 0);
    k1_reduce<<<BCH, 192>>>(sv, mask, qw, BCH);      // b 512..1023
    cudaEventRecord(eB, 0);

    // side stream: k2(c0) after k1a (overlaps k1b); k2(c1) after k1b (overlaps k3c0)
    cudaStreamWaitEvent(s1, eA, 0);
    k2_gemm<<<dim3(Hdim / BN, BCH / BM, 2), 256, K2_SMEM_BYTES, s1>>>(Wrel, Wsim, 0);
    cudaEventRecord(eK0, s1);
    cudaStreamWaitEvent(s1, eB, 0);
    k2_gemm<<<dim3(Hdim / BN, BCH / BM, 2), 256, K2_SMEM_BYTES, s1>>>(Wrel, Wsim, BCH);
    cudaEventRecord(eK1, s1);

    cudaStreamWaitEvent(0, eK0, 0);
    k3_final<<<BCH, 256>>>(sv, mask, Wc, bmat, qb, out, 0);      // b 0..511
    cudaStreamWaitEvent(0, eK1, 0);
    k3_final<<<BCH, 256>>>(sv, mask, Wc, bmat, qb, out, BCH);    // b 512..1023
}

// round 14
// speedup vs baseline: 1.5788x; 1.5788x over previous
#include <cuda_runtime.h>
#include <cstdint>

#define Hdim 768
#define Nn   50
#define Bb   1024

// ---------------- scratch (static device globals; no allocation) ----------------
__device__ float g_drep[Bb * Hdim];
__device__ float g_wvec[Bb * Hdim];
__device__ float g_R[Bb * Hdim];
__device__ float g_G[Bb * Hdim];
__device__ float g_Qm[Bb];

// ---------------- kernel 1: per-batch reductions over n (float4) + Qm ----------------
__global__ __launch_bounds__(192) void k1_reduce(const float* __restrict__ sv,
                                                 const int* __restrict__ mask,
                                                 const float* __restrict__ qw) {
    const int b = blockIdx.x;
    const int t = threadIdx.x;  // 192 threads, one float4 column each
    __shared__ float sq[Nn];
    if (t < Nn) sq[t] = qw[t] * (mask[b * Nn + t] != 0 ? 1.0f : 0.0f);
    __syncthreads();

    const float4* base = (const float4*)(sv + (size_t)b * Nn * Hdim) + t;
    float adx = 0.f, ady = 0.f, adz = 0.f, adw = 0.f;
    float awx = 0.f, awy = 0.f, awz = 0.f, aww = 0.f;
#pragma unroll 10
    for (int n = 0; n < Nn; n++) {
        float4 v = base[n * (Hdim / 4)];
        float s = sq[n];
        adx += v.x; ady += v.y; adz += v.z; adw += v.w;
        awx = fmaf(s, v.x, awx); awy = fmaf(s, v.y, awy);
        awz = fmaf(s, v.z, awz); aww = fmaf(s, v.w, aww);
    }
    const float inv = 1.0f / (float)Nn;
    float4 od = {adx * inv, ady * inv, adz * inv, adw * inv};
    float4 ow = {awx, awy, awz, aww};
    ((float4*)g_drep)[(size_t)b * (Hdim / 4) + t] = od;
    ((float4*)g_wvec)[(size_t)b * (Hdim / 4) + t] = ow;
    if (t == 0) {
        float Qm = 0.0f;
#pragma unroll
        for (int n = 0; n < Nn; n++) Qm += sq[n];
        g_Qm[b] = Qm;
    }
}

// ---------------- kernel 2: tf32 GEMM, BIG tiles, one CTA per SM, single wave ----------------
// z=0: R = d_rep @ W_rel^T   z=1: G = w @ W_sim^T
// BM=128, BN=96 -> grid (8, 8, 2) = 128 CTAs <= 148 SMs (zero wave quantization)
#define BM2 128
#define BN2 96
#define BK 32
#define KPAD 36
#define NKT (Hdim / BK)  // 24
#define NST 3
#define A_STAGE_U32 (BM2 * KPAD)   // 4608
#define B_STAGE_U32 (BN2 * KPAD)   // 3456
#define K2_SMEM_BYTES (NST * (A_STAGE_U32 + B_STAGE_U32) * 4)  // 96768

__device__ __forceinline__ void cp_async16(void* smem_dst, const void* gmem_src) {
    uint32_t d = (uint32_t)__cvta_generic_to_shared(smem_dst);
    asm volatile("cp.async.cg.shared.global [%0], [%1], 16;" ::"r"(d), "l"(gmem_src));
}
__device__ __forceinline__ void cp_commit() { asm volatile("cp.async.commit_group;"); }
template <int N>
__device__ __forceinline__ void cp_wait() { asm volatile("cp.async.wait_group %0;" ::"n"(N)); }

// round-to-nearest tf32 via bit add (HW truncates low 13 bits of tf32 operand)
__device__ __forceinline__ uint32_t rna_bits(uint32_t x) { return x + 0x1000u; }

__device__ __forceinline__ void mma_tf32(float d[4], const uint32_t a[4], const uint32_t b[2]) {
    asm volatile(
        "mma.sync.aligned.m16n8k8.row.col.f32.tf32.tf32.f32 "
        "{%0,%1,%2,%3}, {%4,%5,%6,%7}, {%8,%9}, {%0,%1,%2,%3};"
        : "+f"(d[0]), "+f"(d[1]), "+f"(d[2]), "+f"(d[3])
        : "r"(a[0]), "r"(a[1]), "r"(a[2]), "r"(a[3]), "r"(b[0]), "r"(b[1]));
}

__global__ __launch_bounds__(256) void k2_gemm(const float* __restrict__ Wrel,
                                               const float* __restrict__ Wsim) {
    extern __shared__ uint32_t smem_dyn[];
    uint32_t* As = smem_dyn;                                  // [NST][A_STAGE_U32]
    uint32_t* Bs = smem_dyn + NST * A_STAGE_U32;              // [NST][B_STAGE_U32]

    const int z = blockIdx.z;
    const float* A  = z ? g_wvec : g_drep;
    const float* Bm = z ? Wsim   : Wrel;
    float*       C  = z ? g_G    : g_R;

    const int m0 = blockIdx.y * BM2;
    const int n0 = blockIdx.x * BN2;

    const int tid  = threadIdx.x;     // 256
    const int lane = tid & 31;
    const int wid  = tid >> 5;        // 8 warps: 2 (m) x 4 (n)
    const int wm   = wid >> 2;        // 0..1 -> 64 rows each
    const int wn   = wid & 3;         // 0..3 -> 24 cols each
    const int grp  = lane >> 2;
    const int tg   = lane & 3;

    const int lr  = tid >> 3;   // 0..31
    const int lc4 = tid & 7;    // 0..7

    float acc[4][3][4];
#pragma unroll
    for (int mi = 0; mi < 4; mi++)
#pragma unroll
        for (int ni = 0; ni < 3; ni++)
#pragma unroll
            for (int r = 0; r < 4; r++) acc[mi][ni][r] = 0.0f;

    // prefetch tiles 0,1
#pragma unroll
    for (int pf = 0; pf < 2; pf++) {
        const int k0 = pf * BK;
        uint32_t* Ast = As + pf * A_STAGE_U32;
        uint32_t* Bst = Bs + pf * B_STAGE_U32;
#pragma unroll
        for (int p = 0; p < 4; p++) {   // A: 128 rows
            int r = lr + p * 32;
            cp_async16(&Ast[r * KPAD + lc4 * 4], &A[(size_t)(m0 + r) * Hdim + k0 + lc4 * 4]);
        }
#pragma unroll
        for (int p = 0; p < 3; p++) {   // B: 96 rows
            int r = lr + p * 32;
            cp_async16(&Bst[r * KPAD + lc4 * 4], &Bm[(size_t)(n0 + r) * Hdim + k0 + lc4 * 4]);
        }
        cp_commit();
    }

    for (int kt = 0; kt < NKT; kt++) {
        const int st = kt % NST;
        if (kt + 2 < NKT) {
            const int k0 = (kt + 2) * BK;
            const int ns = (kt + 2) % NST;
            uint32_t* Ast = As + ns * A_STAGE_U32;
            uint32_t* Bst = Bs + ns * B_STAGE_U32;
#pragma unroll
            for (int p = 0; p < 4; p++) {
                int r = lr + p * 32;
                cp_async16(&Ast[r * KPAD + lc4 * 4], &A[(size_t)(m0 + r) * Hdim + k0 + lc4 * 4]);
            }
#pragma unroll
            for (int p = 0; p < 3; p++) {
                int r = lr + p * 32;
                cp_async16(&Bst[r * KPAD + lc4 * 4], &Bm[(size_t)(n0 + r) * Hdim + k0 + lc4 * 4]);
            }
            cp_commit();
            cp_wait<2>();
        } else if (kt + 1 < NKT) {
            cp_wait<1>();
        } else {
            cp_wait<0>();
        }
        __syncthreads();

        const uint32_t* Acur = As + st * A_STAGE_U32;
        const uint32_t* Bcur = Bs + st * B_STAGE_U32;
#pragma unroll
        for (int kk = 0; kk < 4; kk++) {
            const int c0 = kk * 8 + tg;
            uint32_t afr[4][4];
#pragma unroll
            for (int mi = 0; mi < 4; mi++) {
                int r0 = wm * 64 + mi * 16 + grp;
                afr[mi][0] = rna_bits(Acur[r0 * KPAD + c0]);
                afr[mi][1] = rna_bits(Acur[(r0 + 8) * KPAD + c0]);
                afr[mi][2] = rna_bits(Acur[r0 * KPAD + c0 + 4]);
                afr[mi][3] = rna_bits(Acur[(r0 + 8) * KPAD + c0 + 4]);
            }
            uint32_t bfr[3][2];
#pragma unroll
            for (int ni = 0; ni < 3; ni++) {
                int nr = wn * 24 + ni * 8 + grp;
                bfr[ni][0] = rna_bits(Bcur[nr * KPAD + c0]);
                bfr[ni][1] = rna_bits(Bcur[nr * KPAD + c0 + 4]);
            }
#pragma unroll
            for (int mi = 0; mi < 4; mi++)
#pragma unroll
                for (int ni = 0; ni < 3; ni++) mma_tf32(acc[mi][ni], afr[mi], bfr[ni]);
        }
        __syncthreads();
    }

#pragma unroll
    for (int mi = 0; mi < 4; mi++) {
#pragma unroll
        for (int ni = 0; ni < 3; ni++) {
            int row = m0 + wm * 64 + mi * 16 + grp;
            int col = n0 + wn * 24 + ni * 8 + tg * 2;
            *(float2*)&C[(size_t)row * Hdim + col]       = make_float2(acc[mi][ni][0], acc[mi][ni][1]);
            *(float2*)&C[(size_t)(row + 8) * Hdim + col] = make_float2(acc[mi][ni][2], acc[mi][ni][3]);
        }
    }
}

// ---------------- kernel 3: fused single-dot per row + epilogue ----------------
// s[b,n] = q_b + mask*( sv[b,n]·V[b] + b00*Qm ),  V[b] = Qm*(R[b]+Wc) + G[b]
__device__ __forceinline__ float wsum(float v) {
    v += __shfl_xor_sync(0xffffffffu, v, 16);
    v += __shfl_xor_sync(0xffffffffu, v, 8);
    v += __shfl_xor_sync(0xffffffffu, v, 4);
    v += __shfl_xor_sync(0xffffffffu, v, 2);
    v += __shfl_xor_sync(0xffffffffu, v, 1);
    return v;
}

__global__ __launch_bounds__(256, 3) void k3_final(const float* __restrict__ sv,
                                                   const int* __restrict__ mask,
                                                   const float* __restrict__ Wc,
                                                   const float* __restrict__ bmat,
                                                   const float* __restrict__ qb,
                                                   float* __restrict__ out) {
    const int b    = (Bb - 1) - blockIdx.x;   // reverse order for L2 reuse
    const int tid  = threadIdx.x;  // 256
    const int lane = tid & 31;
    const int wid  = tid >> 5;

    __shared__ float sDot[64], sM[64];

    if (tid < 64) sM[tid] = (tid < Nn && mask[b * Nn + tid] != 0) ? 1.0f : 0.0f;
    __syncthreads();

    const float Qm = g_Qm[b];

    // fused per-batch vector V = Qm*(R+Wc) + G, register-resident (lane owns lane+32i)
    float4 rv[6];
    {
        const float4* Wc4 = (const float4*)Wc;
        const float4* Rp  = (const float4*)(g_R + (size_t)b * Hdim);
        const float4* Gp  = (const float4*)(g_G + (size_t)b * Hdim);
#pragma unroll
        for (int i = 0; i < 6; i++) {
            int idx = lane + i * 32;
            float4 c = Wc4[idx], r = Rp[idx], g = Gp[idx];
            rv[i].x = fmaf(Qm, r.x + c.x, g.x);
            rv[i].y = fmaf(Qm, r.y + c.y, g.y);
            rv[i].z = fmaf(Qm, r.z + c.z, g.z);
            rv[i].w = fmaf(Qm, r.w + c.w, g.w);
        }
    }

    // pairs (n, n+8): 12 independent LDG.128 in flight, single dot per row
#pragma unroll
    for (int j = 0; j < 3; j++) {
        const int n0 = wid + j * 16;
        const int n1 = n0 + 8;
        const float4* row0 = (const float4*)(sv + ((size_t)b * Nn + n0) * Hdim);
        const float4* row1 = (const float4*)(sv + ((size_t)b * Nn + n1) * Hdim);
        float d0 = 0.f, d1 = 0.f;
#pragma unroll
        for (int i = 0; i < 6; i++) {
            float4 v0 = row0[lane + i * 32];
            float4 v1 = row1[lane + i * 32];
            d0 = fmaf(v0.x, rv[i].x, d0); d0 = fmaf(v0.y, rv[i].y, d0);
            d0 = fmaf(v0.z, rv[i].z, d0); d0 = fmaf(v0.w, rv[i].w, d0);
            d1 = fmaf(v1.x, rv[i].x, d1); d1 = fmaf(v1.y, rv[i].y, d1);
            d1 = fmaf(v1.z, rv[i].z, d1); d1 = fmaf(v1.w, rv[i].w, d1);
        }
        d0 = wsum(d0); d1 = wsum(d1);
        if (lane == 0) { sDot[n0] = d0; sDot[n1] = d1; }
    }
    {   // leftover n = wid + 48 (only wid 0,1)
        const int n = wid + 48;
        if (n < Nn) {
            const float4* row = (const float4*)(sv + ((size_t)b * Nn + n) * Hdim);
            float d = 0.f;
#pragma unroll
            for (int i = 0; i < 6; i++) {
                float4 v = row[lane + i * 32];
                d = fmaf(v.x, rv[i].x, d); d = fmaf(v.y, rv[i].y, d);
                d = fmaf(v.z, rv[i].z, d); d = fmaf(v.w, rv[i].w, d);
            }
            d = wsum(d);
            if (lane == 0) sDot[n] = d;
        }
    }
    __syncthreads();

    if (wid == 0) {
        const float b00 = bmat[0];
        const float qbv = qb[0];
        const bool  v2  = (lane + 32) < Nn;
        const float m1 = sM[lane], m2 = sM[lane + 32];

        const float sn = wsum(m1 + m2);                  // sent_num
        const float bq = b00 * Qm;

        float s1 = qbv + m1 * (sDot[lane] + bq);
        float s2 = v2 ? (qbv + m2 * (sDot[lane + 32] + bq)) : 0.0f;

        const float mu = wsum(s1 + (v2 ? s2 : 0.0f)) * (1.0f / (float)Nn);
        const float d1 = s1 - mu;
        const float d2 = v2 ? (s2 - mu) : 0.0f;
        const float var = wsum(d1 * d1 + d2 * d2) * (1.0f / (float)Nn);
        const float rstd = rsqrtf(var + 1e-6f);

        const float sig1 = 1.0f / (1.0f + expf(-d1 * rstd));
        const float sig2 = 1.0f / (1.0f + expf(-d2 * rstd));

        const float S = wsum(sig1 * m1 + sig2 * m2);
        const float inv = 1.0f / S;
        const float p1 = sig1 * m1 * inv;
        const float p2 = sig2 * m2 * inv;

        float o1 = (1.0f / (1.0f + expf(-(0.2f + 0.8f * p1 * sn)))) * m1;
        out[b * Nn + lane] = o1;
        if (v2) {
            float o2 = (1.0f / (1.0f + expf(-(0.2f + 0.8f * p2 * sn)))) * m2;
            out[b * Nn + lane + 32] = o2;
        }
    }
}

// ---------------- launch (serial; streams reverted) ----------------
extern "C" void kernel_launch(void* const* d_in, const int* in_sizes, int n_in,
                              void* d_out, int out_size) {
    const float* sv   = (const float*)d_in[0];
    const int*   mask = (const int*)d_in[1];
    const float* Wc   = (const float*)d_in[2];
    const float* Wsim = (const float*)d_in[3];
    const float* Wrel = (const float*)d_in[4];
    const float* bmat = (const float*)d_in[5];
    const float* qw   = (const float*)d_in[6];
    const float* qb   = (const float*)d_in[7];
    float*       out  = (float*)d_out;

    cudaFuncSetAttribute(k2_gemm, cudaFuncAttributeMaxDynamicSharedMemorySize, K2_SMEM_BYTES);

    k1_reduce<<<Bb, 192>>>(sv, mask, qw);
    k2_gemm<<<dim3(Hdim / BN2, Bb / BM2, 2), 256, K2_SMEM_BYTES>>>(Wrel, Wsim);
    k3_final<<<Bb, 256>>>(sv, mask, Wc, bmat, qb, out);
}